// round 4
// baseline (speedup 1.0000x reference)
#include <cuda_runtime.h>

// LIF scan over T=8 timesteps, N = 4,194,304 independent spatial elements.
//   mem = mem*0.25*(1-spike) + x[t]; spike = (mem >= 0.5)
// Pure streaming: 128 MiB read + 128 MiB write, zero reuse -> DRAM-bound.
// R4: occupancy proven non-binding (ncu dur flat across occ 48-84%). Only
// change vs R3: stores switch __stcs -> __stwt (write-through). Output is
// write-once/never-read; write-through avoids accumulating 128 MiB of dirty
// L2 lines whose drain competes with the next graph replay's read stream.

#define DECAY  0.25f
#define THRESH 0.5f

static constexpr int T = 8;

__global__ __launch_bounds__(256) void lif_scan_kernel(
    const float4* __restrict__ x, float4* __restrict__ out, int n4)
{
    int i = blockIdx.x * blockDim.x + threadIdx.x;
    if (i >= n4) return;

    // 8 independent streaming loads (evict-first: zero reuse), MLP=8.
    float4 xv[T];
#pragma unroll
    for (int t = 0; t < T; t++) {
        xv[t] = __ldcs(&x[(size_t)t * n4 + i]);
    }

    float4 mem   = make_float4(0.f, 0.f, 0.f, 0.f);
    float4 spike = make_float4(0.f, 0.f, 0.f, 0.f);

#pragma unroll
    for (int t = 0; t < T; t++) {
        mem.x = mem.x * (DECAY * (1.0f - spike.x)) + xv[t].x;
        mem.y = mem.y * (DECAY * (1.0f - spike.y)) + xv[t].y;
        mem.z = mem.z * (DECAY * (1.0f - spike.z)) + xv[t].z;
        mem.w = mem.w * (DECAY * (1.0f - spike.w)) + xv[t].w;
        spike.x = (mem.x >= THRESH) ? 1.0f : 0.0f;
        spike.y = (mem.y >= THRESH) ? 1.0f : 0.0f;
        spike.z = (mem.z >= THRESH) ? 1.0f : 0.0f;
        spike.w = (mem.w >= THRESH) ? 1.0f : 0.0f;
        __stwt(&out[(size_t)t * n4 + i], spike);
    }
}

extern "C" void kernel_launch(void* const* d_in, const int* in_sizes, int n_in,
                              void* d_out, int out_size)
{
    const float* x = (const float*)d_in[0];
    float* out = (float*)d_out;

    const int total = in_sizes[0];       // T * N
    const int n = total / T;             // elements per timestep (4,194,304)
    const int n4 = n / 4;                // float4 count per timestep (1,048,576)

    const int threads = 256;
    const int blocks = (n4 + threads - 1) / threads;

    lif_scan_kernel<<<blocks, threads>>>(
        (const float4*)x, (float4*)out, n4);
}

// round 5
// speedup vs baseline: 1.0427x; 1.0427x over previous
#include <cuda_runtime.h>

// LIF scan over T=8 timesteps, N = 4,194,304 independent spatial elements.
//   mem = mem*0.25*(1-spike) + x[t]; spike = (mem >= 0.5)
// Pure streaming: 128 MiB read + 128 MiB write, zero reuse -> DRAM-bound.
//
// R5 = R3 re-bench (confirmation run). Evidence so far: ncu kernel time is
// pinned at ~36 us / ~74% DRAM (5.9 TB/s) across occupancy 48-84%, flat vs
// persistent launches, and all cache policies tried; __stwt regressed
// (loses L2 write coalescing). This shape — flat one-float4-per-thread,
// front-batched MLP=8 __ldcs loads, __stcs stores — is the roofline-pinned
// candidate; confirming its timed number is reproducible.

#define DECAY  0.25f
#define THRESH 0.5f

static constexpr int T = 8;

__global__ __launch_bounds__(256) void lif_scan_kernel(
    const float4* __restrict__ x, float4* __restrict__ out, int n4)
{
    int i = blockIdx.x * blockDim.x + threadIdx.x;
    if (i >= n4) return;

    // 8 independent streaming loads (evict-first: zero reuse), MLP=8.
    float4 xv[T];
#pragma unroll
    for (int t = 0; t < T; t++) {
        xv[t] = __ldcs(&x[(size_t)t * n4 + i]);
    }

    float4 mem   = make_float4(0.f, 0.f, 0.f, 0.f);
    float4 spike = make_float4(0.f, 0.f, 0.f, 0.f);

#pragma unroll
    for (int t = 0; t < T; t++) {
        mem.x = mem.x * (DECAY * (1.0f - spike.x)) + xv[t].x;
        mem.y = mem.y * (DECAY * (1.0f - spike.y)) + xv[t].y;
        mem.z = mem.z * (DECAY * (1.0f - spike.z)) + xv[t].z;
        mem.w = mem.w * (DECAY * (1.0f - spike.w)) + xv[t].w;
        spike.x = (mem.x >= THRESH) ? 1.0f : 0.0f;
        spike.y = (mem.y >= THRESH) ? 1.0f : 0.0f;
        spike.z = (mem.z >= THRESH) ? 1.0f : 0.0f;
        spike.w = (mem.w >= THRESH) ? 1.0f : 0.0f;
        __stcs(&out[(size_t)t * n4 + i], spike);
    }
}

extern "C" void kernel_launch(void* const* d_in, const int* in_sizes, int n_in,
                              void* d_out, int out_size)
{
    const float* x = (const float*)d_in[0];
    float* out = (float*)d_out;

    const int total = in_sizes[0];       // T * N
    const int n = total / T;             // elements per timestep (4,194,304)
    const int n4 = n / 4;                // float4 count per timestep (1,048,576)

    const int threads = 256;
    const int blocks = (n4 + threads - 1) / threads;

    lif_scan_kernel<<<blocks, threads>>>(
        (const float4*)x, (float4*)out, n4);
}